// round 12
// baseline (speedup 1.0000x reference)
#include <cuda_runtime.h>

constexpr int Nn = 4096;   // z rows
constexpr int Mm = 1024;   // e rows
constexpr int Dd = 64;     // feature dim

constexpr int NQ = 1024;                     // z-quarter per build block
constexpr int BK = 1024;                     // buckets per quarter
constexpr float LOb  = -6.0f;
constexpr float HIb  =  6.0f;
constexpr float INVW = BK / (HIb - LOb);

__device__ __forceinline__ int bucket_of(float v) {
    int k = (int)((v - LOb) * INVW);
    return min(max(k, 0), BK - 1);
}

// Scratch (no allocations allowed -> device globals)
__device__ float g_pb[4 * Dd * Mm];              // per-query best, 4 z-quarters

// ---------------------------------------------------------------------------
// k1: pure streaming mask + copy. 256 blocks x 256 threads = 65536 threads,
// one float4 per thread. No transposes (k2 gathers directly).
__global__ void __launch_bounds__(256) k1_prep(const float* __restrict__ z,
                                               const int* __restrict__ idx,
                                               float* __restrict__ out) {
    int gid = blockIdx.x * 256 + threadIdx.x;    // 0..65535 float4s
    int row = gid >> 4;                          // z row (D=64 -> 16 quads/row)
    int col = (gid & 15) * 4;
    float4 v = reinterpret_cast<const float4*>(z)[gid];
    int k = idx[row];
    int base = gid * 4;
    // out+1 region is only 4B-aligned -> scalar stores
    out[1 + base + 0] = (col + 0 < k) ? v.x : 0.0f;
    out[1 + base + 1] = (col + 1 < k) ? v.y : 0.0f;
    out[1 + base + 2] = (col + 2 < k) ? v.z : 0.0f;
    out[1 + base + 3] = (col + 3 < k) ? v.w : 0.0f;
    out[1 + Nn * Dd + base + 0] = v.x;
    out[1 + Nn * Dd + base + 1] = v.y;
    out[1 + Nn * Dd + base + 2] = v.z;
    out[1 + Nn * Dd + base + 3] = v.w;
    if (gid == 0) out[0] = 0.0f;
}

// ---------------------------------------------------------------------------
// k2: grid 256 = 64 columns x 4 z-quarters, 2 blocks/SM (full occupancy).
// Block (d,h): gather its 1024-value quarter of column d directly from z
// (strided; L2-resident), bucket it, then thread t answers query m=t from e
// (strided gather): scan own bucket + nearest nonempty bucket each side.
__global__ void __launch_bounds__(1024, 2) k2_nn(const float* __restrict__ z,
                                                 const float* __restrict__ e) {
    __shared__ float S[NQ];          // bucket-grouped quarter (4 KB)
    __shared__ int   cnt[BK];        // hist -> exclusive starts (4 KB)
    __shared__ int   wtot[32];

    const int bx = blockIdx.x;       // 0..255
    const int d  = bx & 63;
    const int h  = bx >> 6;          // which z-quarter
    const int t  = threadIdx.x;
    const int lane = t & 31, wid = t >> 5;

    // Direct gathers (issue both before the first barrier; overlap build).
    float x = e[t * Dd + d];
    float v = z[(h * NQ + t) * Dd + d];

    cnt[t] = 0;
    __syncthreads();

    // ---- histogram + within-bucket rank (1 ATOMS/thread) ----
    int b = bucket_of(v);
    int r = atomicAdd(&cnt[b], 1);
    __syncthreads();

    // ---- block exclusive scan, 1 bucket per thread ----
    int c = cnt[t];
    int inc = c;
    #pragma unroll
    for (int o = 1; o < 32; o <<= 1) {
        int n = __shfl_up_sync(0xFFFFFFFFu, inc, o);
        if (lane >= o) inc += n;
    }
    if (lane == 31) wtot[wid] = inc;
    __syncthreads();
    if (wid == 0) {
        int ws = wtot[lane];
        int wi = ws;
        #pragma unroll
        for (int o = 1; o < 32; o <<= 1) {
            int n = __shfl_up_sync(0xFFFFFFFFu, wi, o);
            if (lane >= o) wi += n;
        }
        wtot[lane] = wi - ws;            // exclusive warp offsets
    }
    __syncthreads();
    cnt[t] = (inc - c) + wtot[wid];      // exclusive start of bucket t
    __syncthreads();

    // ---- scatter: plain store (start + rank unique) ----
    S[cnt[b] + r] = v;
    __syncthreads();

    // ---- query: own bucket + nearest nonempty bucket each side ----
    int k0 = bucket_of(x);
    int start = cnt[k0];
    int end   = (k0 < BK - 1) ? cnt[k0 + 1] : NQ;

    float best = 1e30f;
    for (int j = start; j < end; j++)
        best = fminf(best, fabsf(S[j] - x));

    if (start > 0) {                     // nearest nonempty bucket below
        int bb = bucket_of(S[start - 1]);
        int lo = cnt[bb];                // its segment is [lo, start)
        for (int j = lo; j < start; j++)
            best = fminf(best, fabsf(S[j] - x));
    }
    if (end < NQ) {                      // nearest nonempty bucket above
        int bb = bucket_of(S[end]);
        int hi = (bb < BK - 1) ? cnt[bb + 1] : NQ;
        for (int j = end; j < hi; j++)
            best = fminf(best, fabsf(S[j] - x));
    }

    g_pb[h * (Dd * Mm) + d * Mm + t] = best;   // disjoint plain store
}

// ---------------------------------------------------------------------------
// k3: combine 4 quarters + reduce -> out[0] += sum(min^2) / 65536.
__global__ void __launch_bounds__(1024) k3_reduce(float* __restrict__ out) {
    __shared__ float red[32];
    int i = blockIdx.x * 1024 + threadIdx.x;
    float a = g_pb[i];
    float b = g_pb[Dd * Mm + i];
    float c = g_pb[2 * Dd * Mm + i];
    float d = g_pb[3 * Dd * Mm + i];
    float m = fminf(fminf(a, b), fminf(c, d));
    float val = m * m * (1.0f / (float)(Mm * Dd));
    const int lane = threadIdx.x & 31, wid = threadIdx.x >> 5;
    #pragma unroll
    for (int o = 16; o > 0; o >>= 1)
        val += __shfl_xor_sync(0xFFFFFFFFu, val, o);
    if (lane == 0) red[wid] = val;
    __syncthreads();
    if (wid == 0) {
        float sv = red[lane];
        #pragma unroll
        for (int o = 16; o > 0; o >>= 1)
            sv += __shfl_xor_sync(0xFFFFFFFFu, sv, o);
        if (lane == 0) atomicAdd(out, sv);
    }
}

// ---------------------------------------------------------------------------
extern "C" void kernel_launch(void* const* d_in, const int* in_sizes, int n_in,
                              void* d_out, int out_size) {
    const float* z = (const float*)d_in[0];
    const float* e = (const float*)d_in[1];
    const int* idx = (const int*)d_in[2];
    float* out = (float*)d_out;

    k1_prep<<<256, 256>>>(z, idx, out);
    k2_nn<<<256, 1024>>>(z, e);
    k3_reduce<<<64, 1024>>>(out);
}

// round 13
// speedup vs baseline: 1.0714x; 1.0714x over previous
#include <cuda_runtime.h>

constexpr int Nn = 4096;   // z rows
constexpr int Mm = 1024;   // e rows
constexpr int Dd = 64;     // feature dim

constexpr int NQ = 1024;                     // z-quarter per build block
constexpr int BK = 1024;                     // buckets per quarter
constexpr float LOb  = -6.0f;
constexpr float HIb  =  6.0f;
constexpr float INVW = BK / (HIb - LOb);

__device__ __forceinline__ int bucket_of(float v) {
    int k = (int)((v - LOb) * INVW);
    return min(max(k, 0), BK - 1);
}

// Scratch (no allocations allowed -> device globals)
__device__ __align__(16) float g_zt[Dd * Nn];    // z transposed: [D][N]
__device__ __align__(16) float g_et[Dd * Mm];    // e transposed: [D][M]
__device__ float g_pb[4 * Dd * Mm];              // per-query best, 4 z-quarters

// ---------------------------------------------------------------------------
// k1: 160 blocks x (32,32). 320 tile-units total, 2 per block (u = b, b+160):
//   u < 256 : z 32x32 tile -> mask + copy + transpose into g_zt
//   u >= 256: e 32x32 tile -> transpose into g_et
// Single wave (163840 threads), balanced (every block does exactly 2 units),
// both unit loads issued up front (MLP=2).
__global__ void k1_prep(const float* __restrict__ z, const float* __restrict__ e,
                        const int* __restrict__ idx, float* __restrict__ out) {
    __shared__ float tile[32][33];
    const int b = blockIdx.x;
    const int tx = threadIdx.x, ty = threadIdx.y;

    // ---- unit A: always a z tile (b < 160 < 256) ----
    const int dA = b & 1, nA = b >> 1;             // D-half, N-tile
    const int xA = dA * 32 + tx, yA = nA * 32 + ty;
    float vA = z[yA * Dd + xA];

    // ---- unit B: u = b + 160 (z tile if u < 256, else e tile) ----
    const int u = b + 160;
    const bool Bz = (u < 256);
    int xB, yB;
    if (Bz) { xB = (u & 1) * 32 + tx; yB = (u >> 1) * 32 + ty; }
    else    { int v = u - 256; xB = (v & 1) * 32 + tx; yB = (v >> 1) * 32 + ty; }
    float vB = Bz ? z[yB * Dd + xB] : e[yB * Dd + xB];

    if (b == 0 && tx == 0 && ty == 0) out[0] = 0.0f;

    // ---- process unit A ----
    {
        int k = idx[yA];
        out[1 + yA * Dd + xA]           = (xA < k) ? vA : 0.0f;   // z_masked
        out[1 + Nn * Dd + yA * Dd + xA] = vA;                     // z_copy
        tile[ty][tx] = vA;
        __syncthreads();
        g_zt[(dA * 32 + ty) * Nn + nA * 32 + tx] = tile[tx][ty];
        __syncthreads();
    }

    // ---- process unit B ----
    if (Bz) {
        int k = idx[yB];
        out[1 + yB * Dd + xB]           = (xB < k) ? vB : 0.0f;
        out[1 + Nn * Dd + yB * Dd + xB] = vB;
        tile[ty][tx] = vB;
        __syncthreads();
        g_zt[((u & 1) * 32 + ty) * Nn + (u >> 1) * 32 + tx] = tile[tx][ty];
    } else {
        tile[ty][tx] = vB;
        __syncthreads();
        int v = u - 256;
        g_et[((v & 1) * 32 + ty) * Mm + (v >> 1) * 32 + tx] = tile[tx][ty];
    }
}

// ---------------------------------------------------------------------------
// k2: grid 256 = 64 columns x 4 z-quarters, 2 blocks/SM (full occupancy).
// Block (d,h): bucket its 1024-value quarter (1 value/thread, coalesced from
// g_zt), then thread t answers query m=t (coalesced from g_et): scan own
// bucket + nearest nonempty bucket each side. Plain disjoint store to g_pb.
__global__ void __launch_bounds__(1024, 2) k2_nn() {
    __shared__ float S[NQ];          // bucket-grouped quarter (4 KB)
    __shared__ int   cnt[BK];        // hist -> exclusive starts (4 KB)
    __shared__ int   wtot[32];

    const int bx = blockIdx.x;       // 0..255
    const int d  = bx & 63;
    const int h  = bx >> 6;          // which z-quarter
    const int t  = threadIdx.x;
    const int lane = t & 31, wid = t >> 5;

    // Coalesced prefetches (L2-resident from k1).
    float x = g_et[d * Mm + t];
    float v = g_zt[d * Nn + h * NQ + t];

    cnt[t] = 0;
    __syncthreads();

    // ---- histogram + within-bucket rank (1 ATOMS/thread) ----
    int b = bucket_of(v);
    int r = atomicAdd(&cnt[b], 1);
    __syncthreads();

    // ---- block exclusive scan, 1 bucket per thread ----
    int c = cnt[t];
    int inc = c;
    #pragma unroll
    for (int o = 1; o < 32; o <<= 1) {
        int n = __shfl_up_sync(0xFFFFFFFFu, inc, o);
        if (lane >= o) inc += n;
    }
    if (lane == 31) wtot[wid] = inc;
    __syncthreads();
    if (wid == 0) {
        int ws = wtot[lane];
        int wi = ws;
        #pragma unroll
        for (int o = 1; o < 32; o <<= 1) {
            int n = __shfl_up_sync(0xFFFFFFFFu, wi, o);
            if (lane >= o) wi += n;
        }
        wtot[lane] = wi - ws;            // exclusive warp offsets
    }
    __syncthreads();
    cnt[t] = (inc - c) + wtot[wid];      // exclusive start of bucket t
    __syncthreads();

    // ---- scatter: plain store (start + rank unique) ----
    S[cnt[b] + r] = v;
    __syncthreads();

    // ---- query: own bucket + nearest nonempty bucket each side ----
    int k0 = bucket_of(x);
    int start = cnt[k0];
    int end   = (k0 < BK - 1) ? cnt[k0 + 1] : NQ;

    float best = 1e30f;
    for (int j = start; j < end; j++)
        best = fminf(best, fabsf(S[j] - x));

    if (start > 0) {                     // nearest nonempty bucket below
        int bb = bucket_of(S[start - 1]);
        int lo = cnt[bb];                // its segment is [lo, start)
        for (int j = lo; j < start; j++)
            best = fminf(best, fabsf(S[j] - x));
    }
    if (end < NQ) {                      // nearest nonempty bucket above
        int bb = bucket_of(S[end]);
        int hi = (bb < BK - 1) ? cnt[bb + 1] : NQ;
        for (int j = end; j < hi; j++)
            best = fminf(best, fabsf(S[j] - x));
    }

    g_pb[h * (Dd * Mm) + d * Mm + t] = best;   // disjoint plain store
}

// ---------------------------------------------------------------------------
// k3: combine 4 quarters + reduce -> out[0] += sum(min^2) / 65536.
__global__ void __launch_bounds__(1024) k3_reduce(float* __restrict__ out) {
    __shared__ float red[32];
    int i = blockIdx.x * 1024 + threadIdx.x;
    float a = g_pb[i];
    float b = g_pb[Dd * Mm + i];
    float c = g_pb[2 * Dd * Mm + i];
    float d = g_pb[3 * Dd * Mm + i];
    float m = fminf(fminf(a, b), fminf(c, d));
    float val = m * m * (1.0f / (float)(Mm * Dd));
    const int lane = threadIdx.x & 31, wid = threadIdx.x >> 5;
    #pragma unroll
    for (int o = 16; o > 0; o >>= 1)
        val += __shfl_xor_sync(0xFFFFFFFFu, val, o);
    if (lane == 0) red[wid] = val;
    __syncthreads();
    if (wid == 0) {
        float sv = red[lane];
        #pragma unroll
        for (int o = 16; o > 0; o >>= 1)
            sv += __shfl_xor_sync(0xFFFFFFFFu, sv, o);
        if (lane == 0) atomicAdd(out, sv);
    }
}

// ---------------------------------------------------------------------------
extern "C" void kernel_launch(void* const* d_in, const int* in_sizes, int n_in,
                              void* d_out, int out_size) {
    const float* z = (const float*)d_in[0];
    const float* e = (const float*)d_in[1];
    const int* idx = (const int*)d_in[2];
    float* out = (float*)d_out;

    k1_prep<<<160, dim3(32, 32)>>>(z, e, idx, out);
    k2_nn<<<256, 1024>>>();
    k3_reduce<<<64, 1024>>>(out);
}